// round 3
// baseline (speedup 1.0000x reference)
#include <cuda_runtime.h>
#include <cuda_bf16.h>

// Problem constants (shapes fixed by reference)
#define MAXN 100000
#define FIN  256
#define FOUT 64

// Scratch (device globals — no allocation allowed)
__device__ float g_h[MAXN * FOUT];   // projected features, 25.6 MB (L2-resident)
__device__ float g_as[MAXN];         // a_src per node
__device__ float g_ad[MAXN];         // a_dst per node
__device__ float g_emax[MAXN];       // segment max of leakyrelu(e)
__device__ float g_den[MAXN];        // softmax denominator

static __device__ __forceinline__ float leaky(float v) {
    return v > 0.0f ? v : 0.2f * v;
}

static __device__ __forceinline__ void atomicMaxF(float* addr, float v) {
    // IEEE ordering trick: ints compare like floats for >=0; unsigned reversed for <0
    if (v >= 0.0f) atomicMax((int*)addr, __float_as_int(v));
    else           atomicMin((unsigned int*)addr, __float_as_uint(v));
}

// ---------------------------------------------------------------------------
// K1: h = x @ W   (SGEMM, BM=128, BN=64(=FOUT), BK=16, 8x4 per thread)
// ---------------------------------------------------------------------------
__global__ __launch_bounds__(256) void k_gemm(const float* __restrict__ x,
                                              const float* __restrict__ W,
                                              int n) {
    __shared__ float  As[128][17];       // +1 pad vs 16 to break bank conflicts
    __shared__ float4 Bs[16][16];        // [k][colgroup of 4]

    const int tid  = threadIdx.x;
    const int row0 = blockIdx.x * 128;
    const int tcol = tid & 15;           // 16 col-groups * 4 cols = 64 cols
    const int trow = tid >> 4;           // 16 row-groups * 8 rows = 128 rows

    float acc[8][4];
#pragma unroll
    for (int i = 0; i < 8; i++)
#pragma unroll
        for (int j = 0; j < 4; j++) acc[i][j] = 0.0f;

    for (int k0 = 0; k0 < FIN; k0 += 16) {
        // Load As: 128 rows x 16 k = 512 float4, 2 per thread
#pragma unroll
        for (int l = 0; l < 2; l++) {
            int idx = tid + l * 256;          // 0..511
            int r = idx >> 2, q = idx & 3;
            float4 v = make_float4(0.f, 0.f, 0.f, 0.f);
            int gr = row0 + r;
            if (gr < n)
                v = *(const float4*)(x + (size_t)gr * FIN + k0 + q * 4);
            As[r][q * 4 + 0] = v.x; As[r][q * 4 + 1] = v.y;
            As[r][q * 4 + 2] = v.z; As[r][q * 4 + 3] = v.w;
        }
        // Load Bs: 16 k x 64 cols = 256 float4, 1 per thread
        {
            int k = tid >> 4, cq = tid & 15;
            Bs[k][cq] = *(const float4*)(W + (size_t)(k0 + k) * FOUT + cq * 4);
        }
        __syncthreads();

#pragma unroll
        for (int kk = 0; kk < 16; kk++) {
            float4 b = Bs[kk][tcol];
#pragma unroll
            for (int i = 0; i < 8; i++) {
                float a = As[trow + 16 * i][kk];
                acc[i][0] += a * b.x;
                acc[i][1] += a * b.y;
                acc[i][2] += a * b.z;
                acc[i][3] += a * b.w;
            }
        }
        __syncthreads();
    }

#pragma unroll
    for (int i = 0; i < 8; i++) {
        int r = row0 + trow + 16 * i;
        if (r < n) {
            float4 v = make_float4(acc[i][0], acc[i][1], acc[i][2], acc[i][3]);
            *(float4*)(g_h + (size_t)r * FOUT + tcol * 4) = v;
        }
    }
}

// ---------------------------------------------------------------------------
// K2: per-node attention halves + init (one warp per node)
//     a_src[i], a_dst[i]; e_max init = leakyrelu(self-loop logit); den = 0
// ---------------------------------------------------------------------------
__global__ __launch_bounds__(256) void k_attn(const float* __restrict__ att_src,
                                              const float* __restrict__ att_dst,
                                              int n) {
    int warp = (blockIdx.x * blockDim.x + threadIdx.x) >> 5;
    int lane = threadIdx.x & 31;
    if (warp >= n) return;
    const float* hr = g_h + (size_t)warp * FOUT;
    float h0 = hr[lane], h1 = hr[lane + 32];
    float s = h0 * __ldg(att_src + lane) + h1 * __ldg(att_src + lane + 32);
    float d = h0 * __ldg(att_dst + lane) + h1 * __ldg(att_dst + lane + 32);
#pragma unroll
    for (int o = 16; o > 0; o >>= 1) {
        s += __shfl_xor_sync(0xFFFFFFFFu, s, o);
        d += __shfl_xor_sync(0xFFFFFFFFu, d, o);
    }
    if (lane == 0) {
        g_as[warp] = s;
        g_ad[warp] = d;
        g_emax[warp] = leaky(s + d);  // self-loop included in segment max
        g_den[warp]  = 0.0f;
    }
}

// ---------------------------------------------------------------------------
// K3: segment max over real edges (self-loop already in init)
// ---------------------------------------------------------------------------
__global__ __launch_bounds__(256) void k_max(const int* __restrict__ ei, int e) {
    int idx = blockIdx.x * blockDim.x + threadIdx.x;
    if (idx >= e) return;
    int s = ei[idx], d = ei[e + idx];
    float v = leaky(g_as[s] + g_ad[d]);
    atomicMaxF(&g_emax[d], v);
}

// ---------------------------------------------------------------------------
// K4: softmax denominator (E real edges + N self-loops)
// ---------------------------------------------------------------------------
__global__ __launch_bounds__(256) void k_den(const int* __restrict__ ei, int e, int n) {
    int idx = blockIdx.x * blockDim.x + threadIdx.x;
    if (idx < e) {
        int s = ei[idx], d = ei[e + idx];
        float v = leaky(g_as[s] + g_ad[d]);
        atomicAdd(&g_den[d], __expf(v - g_emax[d]));
    } else {
        int i = idx - e;
        if (i < n) {
            float v = leaky(g_as[i] + g_ad[i]);
            atomicAdd(&g_den[i], __expf(v - g_emax[i]));
        }
    }
}

// ---------------------------------------------------------------------------
// K5: init out with self-loop contribution + bias
// ---------------------------------------------------------------------------
__global__ __launch_bounds__(256) void k_init(float* __restrict__ out,
                                              const float* __restrict__ bias,
                                              int n) {
    int idx = blockIdx.x * blockDim.x + threadIdx.x;
    if (idx >= n * FOUT) return;
    int i = idx >> 6, c = idx & 63;
    float v = leaky(g_as[i] + g_ad[i]);
    float alpha = __expf(v - g_emax[i]) / (g_den[i] + 1e-16f);
    out[idx] = alpha * g_h[idx] + __ldg(bias + c);
}

// ---------------------------------------------------------------------------
// K6: aggregation — 16 threads per edge, float4 gather + red.global.add.v4.f32
// ---------------------------------------------------------------------------
__global__ __launch_bounds__(256) void k_agg(const int* __restrict__ ei,
                                             float* __restrict__ out, int e) {
    int gid  = blockIdx.x * blockDim.x + threadIdx.x;
    int edge = gid >> 4;
    int sub  = gid & 15;
    if (edge >= e) return;
    int s = ei[edge], d = ei[e + edge];
    float v = leaky(g_as[s] + g_ad[d]);
    float alpha = __expf(v - g_emax[d]) / (g_den[d] + 1e-16f);
    const float4 hv = *(const float4*)(g_h + (size_t)s * FOUT + sub * 4);
    float* dst = out + (size_t)d * FOUT + sub * 4;
    asm volatile("red.global.add.v4.f32 [%0], {%1, %2, %3, %4};"
                 :: "l"(dst), "f"(alpha * hv.x), "f"(alpha * hv.y),
                    "f"(alpha * hv.z), "f"(alpha * hv.w)
                 : "memory");
}

// ---------------------------------------------------------------------------
// Launch
// ---------------------------------------------------------------------------
extern "C" void kernel_launch(void* const* d_in, const int* in_sizes, int n_in,
                              void* d_out, int out_size) {
    const float* x       = (const float*)d_in[0];
    const int*   ei      = (const int*)d_in[1];
    const float* W       = (const float*)d_in[2];
    const float* att_src = (const float*)d_in[3];
    const float* att_dst = (const float*)d_in[4];
    const float* bias    = (const float*)d_in[5];
    float* out = (float*)d_out;

    const int n = in_sizes[0] / FIN;     // 100000
    const int e = in_sizes[1] / 2;       // 3200000

    // K1: projection
    k_gemm<<<(n + 127) / 128, 256>>>(x, W, n);
    // K2: attention halves + inits
    k_attn<<<(n + 7) / 8, 256>>>(att_src, att_dst, n);
    // K3: segment max
    k_max<<<(e + 255) / 256, 256>>>(ei, e);
    // K4: denominator (edges + self-loops)
    k_den<<<(e + n + 255) / 256, 256>>>(ei, e, n);
    // K5: out init = self-loop term + bias
    k_init<<<(n * FOUT + 255) / 256, 256>>>(out, bias, n);
    // K6: edge aggregation
    {
        long long total = (long long)e * 16;
        int blocks = (int)((total + 255) / 256);
        k_agg<<<blocks, 256>>>(ei, out, e);
    }
}

// round 5
// speedup vs baseline: 1.1835x; 1.1835x over previous
#include <cuda_runtime.h>
#include <cuda_bf16.h>

#define MAXN 100000
#define FIN  256
#define FOUT 64

// Scratch (device globals — allocation is forbidden)
__device__ float g_h[MAXN * FOUT];   // projected features (25.6 MB, L2-resident)
__device__ float g_as[MAXN];         // h · att_src
__device__ float g_ad[MAXN];         // h · att_dst
__device__ float g_den[MAXN];        // Σ p over incoming real edges

static __device__ __forceinline__ float leaky(float v) {
    return v > 0.0f ? v : 0.2f * v;
}

// ---------------------------------------------------------------------------
// K1: h = x @ W  (BM=128, BN=64, BK=16, 8x4/thread) + fused epilogue:
//     a_src, a_dst per row, den init = 0
// ---------------------------------------------------------------------------
__global__ __launch_bounds__(256) void k_gemm(const float* __restrict__ x,
                                              const float* __restrict__ W,
                                              const float* __restrict__ att_src,
                                              const float* __restrict__ att_dst,
                                              int n) {
    __shared__ float  As[128][17];
    __shared__ float4 Bs[16][16];

    const int tid  = threadIdx.x;
    const int row0 = blockIdx.x * 128;
    const int tcol = tid & 15;
    const int trow = tid >> 4;

    float acc[8][4];
#pragma unroll
    for (int i = 0; i < 8; i++)
#pragma unroll
        for (int j = 0; j < 4; j++) acc[i][j] = 0.0f;

    for (int k0 = 0; k0 < FIN; k0 += 16) {
#pragma unroll
        for (int l = 0; l < 2; l++) {
            int idx = tid + l * 256;
            int r = idx >> 2, q = idx & 3;
            float4 v = make_float4(0.f, 0.f, 0.f, 0.f);
            int gr = row0 + r;
            if (gr < n)
                v = *(const float4*)(x + (size_t)gr * FIN + k0 + q * 4);
            As[r][q * 4 + 0] = v.x; As[r][q * 4 + 1] = v.y;
            As[r][q * 4 + 2] = v.z; As[r][q * 4 + 3] = v.w;
        }
        {
            int k = tid >> 4, cq = tid & 15;
            Bs[k][cq] = *(const float4*)(W + (size_t)(k0 + k) * FOUT + cq * 4);
        }
        __syncthreads();

#pragma unroll
        for (int kk = 0; kk < 16; kk++) {
            float4 b = Bs[kk][tcol];
#pragma unroll
            for (int i = 0; i < 8; i++) {
                float a = As[trow + 16 * i][kk];
                acc[i][0] += a * b.x;
                acc[i][1] += a * b.y;
                acc[i][2] += a * b.z;
                acc[i][3] += a * b.w;
            }
        }
        __syncthreads();
    }

    // att vector slices for this thread's 4 columns
    const float4 asv = *(const float4*)(att_src + tcol * 4);
    const float4 adv = *(const float4*)(att_dst + tcol * 4);

#pragma unroll
    for (int i = 0; i < 8; i++) {
        int r = row0 + trow + 16 * i;
        // partial attention dots for this row
        float sa = acc[i][0] * asv.x + acc[i][1] * asv.y
                 + acc[i][2] * asv.z + acc[i][3] * asv.w;
        float sd = acc[i][0] * adv.x + acc[i][1] * adv.y
                 + acc[i][2] * adv.z + acc[i][3] * adv.w;
#pragma unroll
        for (int o = 8; o > 0; o >>= 1) {
            sa += __shfl_xor_sync(0xFFFFFFFFu, sa, o);
            sd += __shfl_xor_sync(0xFFFFFFFFu, sd, o);
        }
        if (r < n) {
            *(float4*)(g_h + (size_t)r * FOUT + tcol * 4) =
                make_float4(acc[i][0], acc[i][1], acc[i][2], acc[i][3]);
            if (tcol == 0) {
                g_as[r]  = sa;
                g_ad[r]  = sd;
                g_den[r] = 0.0f;
            }
        }
    }
}

// ---------------------------------------------------------------------------
// K2: fused edge pass — 16 threads/edge.
//     Lane sub==0 computes p = exp(leakyrelu(a_src[s]+a_dst[d])), shuffles to
//     the group, reds den[d] += p; all 16 red p·h[s] into out[d].
// ---------------------------------------------------------------------------
__global__ __launch_bounds__(256) void k_edge(const int* __restrict__ ei,
                                              float* __restrict__ out, int e) {
    unsigned gid  = blockIdx.x * 256u + threadIdx.x;
    int edge = (int)(gid >> 4);
    if (edge >= e) return;
    int sub  = (int)(gid & 15);
    int lane = threadIdx.x & 31;

    int s = __ldg(ei + edge);
    int d = __ldg(ei + e + edge);

    float p = 0.0f;
    if (sub == 0)
        p = __expf(leaky(g_as[s] + g_ad[d]));
    p = __shfl_sync(0xFFFFFFFFu, p, lane & 16);   // lane 0 / lane 16 broadcast
    if (sub == 0)
        atomicAdd(&g_den[d], p);                  // compiles to RED (no return)

    const float4 hv = *(const float4*)(g_h + (size_t)s * FOUT + sub * 4);
    float* dst = out + (size_t)d * FOUT + sub * 4;
    asm volatile("red.global.add.v4.f32 [%0], {%1, %2, %3, %4};"
                 :: "l"(dst), "f"(p * hv.x), "f"(p * hv.y),
                    "f"(p * hv.z), "f"(p * hv.w)
                 : "memory");
}

// ---------------------------------------------------------------------------
// K3: finalize — add self-loop, normalize, add bias
//     out[i] = (acc[i] + p_i*h[i]) / (den[i] + p_i + 1e-16) + bias
// ---------------------------------------------------------------------------
__global__ __launch_bounds__(256) void k_fin(float* __restrict__ out,
                                             const float* __restrict__ bias,
                                             int n) {
    int idx = blockIdx.x * blockDim.x + threadIdx.x;
    if (idx >= n * FOUT) return;
    int i = idx >> 6, c = idx & 63;
    float p = __expf(leaky(g_as[i] + g_ad[i]));   // self-loop weight
    float inv = 1.0f / (g_den[i] + p + 1e-16f);
    out[idx] = (out[idx] + p * g_h[idx]) * inv + __ldg(bias + c);
}

// ---------------------------------------------------------------------------
extern "C" void kernel_launch(void* const* d_in, const int* in_sizes, int n_in,
                              void* d_out, int out_size) {
    const float* x       = (const float*)d_in[0];
    const int*   ei      = (const int*)d_in[1];
    const float* W       = (const float*)d_in[2];
    const float* att_src = (const float*)d_in[3];
    const float* att_dst = (const float*)d_in[4];
    const float* bias    = (const float*)d_in[5];
    float* out = (float*)d_out;

    const int n = in_sizes[0] / FIN;   // 100000
    const int e = in_sizes[1] / 2;     // 3200000

    // zero the output accumulator (graph-capturable)
    cudaMemsetAsync(out, 0, (size_t)n * FOUT * sizeof(float));

    // K1: projection + attention halves + den init
    k_gemm<<<(n + 127) / 128, 256>>>(x, W, att_src, att_dst, n);

    // K2: single fused edge pass (unnormalized accumulate + denominator)
    {
        long long total = (long long)e * 16;
        int blocks = (int)((total + 255) / 256);
        k_edge<<<blocks, 256>>>(ei, out, e);
    }

    // K3: self-loop + normalize + bias
    k_fin<<<(n * FOUT + 255) / 256, 256>>>(out, bias, n);
}